// round 16
// baseline (speedup 1.0000x reference)
#include <cuda_runtime.h>
#include <cuda_fp16.h>
#include <mma.h>
#include <math.h>
#include <stdint.h>

using namespace nvcuda;

#define NB   128
#define CIN  128
#define TIN  2500
#define CO   64
#define KW   27
#define TOUT 625
#define KTOT (CIN * KW)      // 3456
#define NKB2 54              // chunks of 64 K

// ---------------- scratch (device globals; no allocation) ----------------
__device__ int4   d_bfrag[NKB2 * 4 * 4 * 32];      // pre-fragmented conv B (442KB)
__device__ unsigned long long d_ktab64[NKB2 * 8];  // per-K byte: (s<<6)|(r<<4)|a
__device__ float  d_scale[CO];
__device__ float  d_shift[CO];
__device__ float  d_y [NB * CO * TOUT];
__device__ __half d_qh[NB * TOUT * CO];       // (B,T,C)
__device__ __half d_kh[NB * CO * TOUT];       // (B,C,T)
__device__ __half d_vh[NB * TOUT * CO];       // (B,T,C)
__device__ __half d_wqkvh[192 * 128];
__device__ float  d_wot[CO * CO];

__device__ __forceinline__ uint32_t smem_u32(const void* p) {
    uint32_t a;
    asm("{ .reg .u64 t; cvta.to.shared.u64 t, %1; cvt.u32.u64 %0, t; }" : "=r"(a) : "l"(p));
    return a;
}
__device__ __forceinline__ void mma16816(float* c, uint32_t a0, uint32_t a1,
                                         uint32_t a2, uint32_t a3,
                                         uint32_t b0, uint32_t b1) {
    asm volatile(
        "mma.sync.aligned.m16n8k16.row.col.f32.f16.f16.f32 "
        "{%0,%1,%2,%3}, {%4,%5,%6,%7}, {%8,%9}, {%0,%1,%2,%3};"
        : "+f"(c[0]), "+f"(c[1]), "+f"(c[2]), "+f"(c[3])
        : "r"(a0), "r"(a1), "r"(a2), "r"(a3), "r"(b0), "r"(b1));
}

// ---------------- prep ----------------
__global__ void prep_weights(const float* __restrict__ w,
                             const float* __restrict__ cb,
                             const float* __restrict__ gamma,
                             const float* __restrict__ beta,
                             const float* __restrict__ mean,
                             const float* __restrict__ var) {
    int o = blockIdx.x;
    __shared__ float red[256];
    const float* wrow = w + o * KTOT;
    float s = 0.f;
    for (int j = threadIdx.x; j < KTOT; j += 256) s += fabsf(wrow[j]);
    red[threadIdx.x] = s;
    __syncthreads();
    for (int st = 128; st > 0; st >>= 1) {
        if (threadIdx.x < st) red[threadIdx.x] += red[threadIdx.x + st];
        __syncthreads();
    }
    float alpha = red[0] * (1.f / KTOT);
    float g = gamma[o] * rsqrtf(var[o] + 1e-5f);
    if (threadIdx.x == 0) {
        d_scale[o] = alpha * g;
        d_shift[o] = (cb[o] - mean[o]) * g + beta[o];
    }
}

// B fragments in mma.m16n8k16 B-operand lane order, built from sign(w).
__global__ void prep_bfrag(const float* __restrict__ w) {
    int idx = blockIdx.x * 256 + threadIdx.x;     // 0..27647
    if (idx >= NKB2 * 4 * 4 * 32) return;
    int lane = idx & 31;
    int np   = (idx >> 5) & 3;
    int kk   = (idx >> 7) & 3;
    int ib   = idx >> 9;
    int Kb  = ib * 64 + kk * 16 + (lane & 3) * 2;
    int n_a = np * 16 + (lane >> 2);
    int n_b = n_a + 8;
    auto sgn = [&](int K, int o) -> uint32_t {
        float v = w[o * KTOT + K];
        return (v > 0.f) ? 0x3C00u : ((v < 0.f) ? 0xBC00u : 0u);
    };
    int4 r;
    r.x = (int)(sgn(Kb, n_a)     | (sgn(Kb + 1, n_a) << 16));
    r.y = (int)(sgn(Kb + 8, n_a) | (sgn(Kb + 9, n_a) << 16));
    r.z = (int)(sgn(Kb, n_b)     | (sgn(Kb + 1, n_b) << 16));
    r.w = (int)(sgn(Kb + 8, n_b) | (sgn(Kb + 9, n_b) << 16));
    d_bfrag[idx] = r;
}

__global__ void prep_misc(const float* __restrict__ wq, const float* __restrict__ wk,
                          const float* __restrict__ wv, const float* __restrict__ wo) {
    int gtid = blockIdx.x * blockDim.x + threadIdx.x;
    int gstr = gridDim.x * blockDim.x;
    for (int j = gtid; j < CO * CO; j += gstr) {
        int o = j >> 6, c = j & 63;
        d_wot[c * CO + o] = wo[j];
    }
    for (int j = gtid; j < 192 * 128; j += gstr) {
        int m = j >> 7, k = j & 127;
        float v = 0.f;
        if (m < 64)        { if (k < 64)  v = wq[m * 64 + k]; }
        else if (m < 128)  { if (k < 64)  v = wk[(m - 64) * 64 + k]; }
        else               { if (k >= 64) v = wv[(m - 128) * 64 + (k - 64)]; }
        d_wqkvh[j] = __float2half(v);
    }
    for (int K = gtid; K < KTOT; K += gstr) {
        int ib = K >> 6, e = K & 63;
        int ci = K / 27, k = K - 27 * ci;
        int s  = ci - (64 * ib) / 27;        // 0..3
        ((uint8_t*)d_ktab64)[ib * 64 + e] =
            (uint8_t)((s << 6) | ((k & 3) << 4) | (k >> 2));
    }
}

// ---------------- raw-mma fp16 implicit-GEMM conv + BN + ELU ----------------
// grid (10, 128), 128 threads. Window double-buffered; B comes pre-fragmented
// from gmem (no B smem at all). One sync per iteration.
#define W_OFF    0                    // 2 x 1152 floats = 9216
#define KOFF_OFF 9216                 // 2 x 64 ints = 512
#define SM_CONV  17664                // Cs alias 64*68*4 = 17408 at 0

__global__ __launch_bounds__(128) void conv_mma(const float* __restrict__ x) {
    extern __shared__ char smem[];
    float*  Wb     = (float*)(smem + W_OFF);      // [buf][slot*288 + r*72 + a]
    int*    koff_s = (int*)(smem + KOFF_OFF);     // [buf][64]
    float*  Cs     = (float*)smem;                // epilogue alias 64x68

    int tid = threadIdx.x, wid = tid >> 5, lid = tid & 31;
    int t0 = blockIdx.x * 64;
    int b  = blockIdx.y;
    int w0 = 4 * t0 - 13;

    const float* xb = x + (size_t)b * CIN * TIN;

    float acc[8][4];
    #pragma unroll
    for (int f = 0; f < 8; f++)
        #pragma unroll
        for (int j = 0; j < 4; j++) acc[f][j] = 0.f;

    int tA = wid * 16 + (lid >> 2);

    float wreg[9];
    int   kreg;

    auto load_regs = [&](int ibn) {
        int ci0 = (64 * ibn) / 27;
        #pragma unroll
        for (int i = 0; i < 9; i++) {
            int j2 = tid + i * 128;
            float v = 0.f;
            if (j2 < 1152) {
                int slot = j2 / 288, j = j2 - slot * 288;
                int ci = ci0 + slot, gp = w0 + j;
                if (j < 279 && ci < CIN && (unsigned)gp < (unsigned)TIN)
                    v = __ldg(xb + ci * TIN + gp);
            }
            wreg[i] = v;
        }
        kreg = (tid < 64) ? ((const uint8_t*)d_ktab64)[ibn * 64 + tid] : 0;
    };

    auto sts = [&](int buf) {
        float* W = Wb + buf * 1152;
        #pragma unroll
        for (int i = 0; i < 9; i++) {
            int j2 = tid + i * 128;
            if (j2 < 1152) {
                int slot = j2 / 288, j = j2 - slot * 288;
                W[slot * 288 + (j & 3) * 72 + (j >> 2)] = wreg[i];
            }
        }
        if (tid < 64)
            koff_s[buf * 64 + tid] =
                (kreg >> 6) * 288 + ((kreg >> 4) & 3) * 72 + (kreg & 15);
    };

    auto compute = [&](int buf, int ib) {
        const float* W  = Wb + buf * 1152;
        const int*   ko = koff_s + buf * 64;
        #pragma unroll
        for (int kk = 0; kk < 4; kk++) {
            int kb0 = kk * 16 + (lid & 3) * 2;
            int o0 = ko[kb0], o1 = ko[kb0 + 1];
            int o2 = ko[kb0 + 8], o3 = ko[kb0 + 9];
            __half2 h;
            uint32_t a0, a1, a2, a3;
            h = __floats2half2_rn(W[o0 + tA],     W[o1 + tA]);     a0 = *(uint32_t*)&h;
            h = __floats2half2_rn(W[o0 + tA + 8], W[o1 + tA + 8]); a1 = *(uint32_t*)&h;
            h = __floats2half2_rn(W[o2 + tA],     W[o3 + tA]);     a2 = *(uint32_t*)&h;
            h = __floats2half2_rn(W[o2 + tA + 8], W[o3 + tA + 8]); a3 = *(uint32_t*)&h;

            const int4* bf = d_bfrag + (ib * 4 + kk) * 128 + lid;
            #pragma unroll
            for (int np = 0; np < 4; np++) {
                int4 bb = __ldg(bf + np * 32);
                mma16816(acc[np * 2],     a0, a1, a2, a3, (uint32_t)bb.x, (uint32_t)bb.y);
                mma16816(acc[np * 2 + 1], a0, a1, a2, a3, (uint32_t)bb.z, (uint32_t)bb.w);
            }
        }
    };

    load_regs(0);
    sts(0);
    __syncthreads();

    for (int ib = 0; ib < NKB2; ib++) {
        int buf = ib & 1;
        if (ib + 1 < NKB2) load_regs(ib + 1);
        compute(buf, ib);
        if (ib + 1 < NKB2) sts(buf ^ 1);
        __syncthreads();
    }

    {
        int r = wid * 16 + (lid >> 2);
        int cb2 = (lid & 3) * 2;
        #pragma unroll
        for (int f = 0; f < 8; f++) {
            int c = f * 8 + cb2;
            Cs[r * 68 + c]           = acc[f][0];
            Cs[r * 68 + c + 1]       = acc[f][1];
            Cs[(r + 8) * 68 + c]     = acc[f][2];
            Cs[(r + 8) * 68 + c + 1] = acc[f][3];
        }
    }
    __syncthreads();

    #pragma unroll
    for (int it = 0; it < 32; it++) {
        int idx = it * 128 + tid;
        int o  = idx >> 6;
        int tl = idx & 63;
        int t  = t0 + tl;
        if (t < TOUT) {
            float v = Cs[tl * 68 + o] * __ldg(d_scale + o) + __ldg(d_shift + o);
            v = (v > 0.f) ? v : expm1f(v);
            d_y[((size_t)b * CO + o) * TOUT + t] = v;
        }
    }
}

// ---------------- qkv as one wmma GEMM: [192x128] x [128x64] ----------------
#define BLD  72
#define QB_OFF 0
#define QA_OFF 18432
#define QC_OFF 18432
#define SM_QKV (18432 + 52224)

__global__ __launch_bounds__(256) void qkv_gemm() {
    extern __shared__ char smem[];
    __half* Bh = (__half*)(smem + QB_OFF);
    __half* Ah = (__half*)(smem + QA_OFF);
    float*  Cs = (float*)(smem + QC_OFF);

    int t0  = blockIdx.x * 64;
    int b   = blockIdx.y;
    int tid = threadIdx.x;
    int wid = tid >> 5;
    int warp_m = wid & 3;
    int warp_n = wid >> 2;

    for (int j = tid; j < 4096; j += 256) {
        int c = j >> 6, tl = j & 63;
        int t = t0 + tl;
        float yv = (t < TOUT) ? d_y[((size_t)b * CO + c) * TOUT + t] : 0.f;
        Bh[c * BLD + tl]        = __float2half(yv > 0.f ? 1.f : 0.f);
        Bh[(64 + c) * BLD + tl] = __float2half(yv);
    }
    {
        const int4* asrc = (const int4*)d_wqkvh;
        #pragma unroll
        for (int e = 0; e < 12; e++) {
            int idx = tid + e * 256;
            int m = idx >> 4, seg = idx & 15;
            *(int4*)&Ah[m * 136 + seg * 8] = __ldg(asrc + idx);
        }
    }
    __syncthreads();

    wmma::fragment<wmma::accumulator, 16, 16, 16, float> acc[3][2];
    #pragma unroll
    for (int i = 0; i < 3; i++)
        #pragma unroll
        for (int j = 0; j < 2; j++) wmma::fill_fragment(acc[i][j], 0.f);

    #pragma unroll
    for (int kk = 0; kk < 8; kk++) {
        wmma::fragment<wmma::matrix_a, 16, 16, 16, __half, wmma::row_major> af[3];
        wmma::fragment<wmma::matrix_b, 16, 16, 16, __half, wmma::row_major> bf[2];
        #pragma unroll
        for (int i = 0; i < 3; i++)
            wmma::load_matrix_sync(af[i], Ah + (warp_m * 48 + i * 16) * 136 + kk * 16, 136);
        #pragma unroll
        for (int j = 0; j < 2; j++)
            wmma::load_matrix_sync(bf[j], Bh + (kk * 16) * BLD + warp_n * 32 + j * 16, BLD);
        #pragma unroll
        for (int i = 0; i < 3; i++)
            #pragma unroll
            for (int j = 0; j < 2; j++)
                wmma::mma_sync(acc[i][j], af[i], bf[j], acc[i][j]);
    }
    __syncthreads();

    #pragma unroll
    for (int i = 0; i < 3; i++)
        #pragma unroll
        for (int j = 0; j < 2; j++)
            wmma::store_matrix_sync(Cs + (warp_m * 48 + i * 16) * 68 + warp_n * 32 + j * 16,
                                    acc[i][j], 68, wmma::mem_row_major);
    __syncthreads();

    for (int j = tid; j < 4096; j += 256) {
        int tl = j >> 6, o = j & 63;
        int t = t0 + tl;
        if (t < TOUT) d_qh[((size_t)b * TOUT + t) * CO + o] = __float2half(Cs[o * 68 + tl]);
    }
    for (int j = tid; j < 4096; j += 256) {
        int o = j >> 6, tl = j & 63;
        int t = t0 + tl;
        if (t < TOUT) d_kh[((size_t)b * CO + o) * TOUT + t] = __float2half(Cs[(64 + o) * 68 + tl]);
    }
    for (int j = tid; j < 4096; j += 256) {
        int tl = j >> 6, o = j & 63;
        int t = t0 + tl;
        if (t < TOUT) d_vh[((size_t)b * TOUT + t) * CO + o] = __float2half(Cs[(128 + o) * 68 + tl]);
    }
}

// ---------------- raw-mma attention: register softmax, no S/P smem ----------------
// 8 warps: warp_m = wid&3 (16 q rows), warp_h = wid>>2 (32-col s half).
// Q fragments persistent in regs; S C-frag reused directly as PV A-frag.
#define AK_OFF   17472               // Kh 64x72 half (Sf alias occupies 0..17408)
#define AV_OFF   (AK_OFF + 9216)     // Vh 64x72 half
#define ARL_OFF  (AV_OFF + 9216)     // redl 128 floats
#define SM_ATT2  (ARL_OFF + 512)

__global__ __launch_bounds__(256) void attn_mma(float* __restrict__ out) {
    extern __shared__ char smem[];
    __half* Qh   = (__half*)smem;               // 64x72 (freed after frag extract)
    float*  Sf   = (float*)smem;                // 64x68 epilogue alias
    __half* Kh   = (__half*)(smem + AK_OFF);    // [c][s]
    __half* Vh   = (__half*)(smem + AV_OFF);    // [s][c]
    float*  redl = (float*)(smem + ARL_OFF);    // [2][64]
    float*  wot_s = (float*)(smem + AK_OFF);    // epilogue alias (16KB over Kh+Vh)

    int t0 = blockIdx.x * 64, b = blockIdx.y;
    int tid = threadIdx.x, wid = tid >> 5, lid = tid & 31;
    int warp_m = wid & 3, warp_h = wid >> 2;
    int gid = lid >> 2, tig = lid & 3;
    int g = lid >> 3, i5 = lid & 7;
    int lm_krow = i5 + (g & 1) * 8;
    int lm_ncol = (g >> 1) * 8;

    // ---- Q tile -> smem -> persistent A fragments
    for (int j = tid; j < 4096; j += 256) {
        int tl = j >> 6, c = j & 63;
        int t = t0 + tl;
        Qh[tl * 72 + c] = (t < TOUT) ? d_qh[((size_t)b * TOUT + t) * CO + c]
                                     : __float2half(0.f);
    }
    __syncthreads();
    uint32_t qf[4][4];
    {
        uint32_t Qbase = smem_u32(Qh);
        #pragma unroll
        for (int kk = 0; kk < 4; kk++) {
            int row = warp_m * 16 + (lid & 15);
            int col = kk * 16 + (lid >> 4) * 8;
            uint32_t addr = Qbase + (uint32_t)((row * 72 + col) * 2);
            asm volatile("ldmatrix.sync.aligned.m8n8.x4.shared.b16 {%0,%1,%2,%3}, [%4];"
                : "=r"(qf[kk][0]), "=r"(qf[kk][1]), "=r"(qf[kk][2]), "=r"(qf[kk][3])
                : "r"(addr));
        }
    }

    float ctx[8][4];
    #pragma unroll
    for (int f = 0; f < 8; f++)
        #pragma unroll
        for (int j = 0; j < 4; j++) ctx[f][j] = 0.f;
    float l0 = 0.f, l1 = 0.f;

    uint32_t Kbase = smem_u32(Kh);
    uint32_t Vbase = smem_u32(Vh);

    for (int st = 0; st < 10; st++) {
        int s0 = st * 64;
        __syncthreads();           // prior stile's ldmatrix reads done (covers Q load too)
        for (int j = tid; j < 4096; j += 256) {
            int c = j >> 6, sl = j & 63;
            int s = s0 + sl;
            Kh[c * 72 + sl] = (s < TOUT) ? d_kh[((size_t)b * CO + c) * TOUT + s]
                                         : __float2half(0.f);
        }
        for (int j = tid; j < 4096; j += 256) {
            int sl = j >> 6, c = j & 63;
            int s = s0 + sl;
            Vh[sl * 72 + c] = (s < TOUT) ? d_vh[((size_t)b * TOUT + s) * CO + c]
                                         : __float2half(0.f);
        }
        __syncthreads();

        // ---- S = Q K   (warp: 16 q-rows x 32 s-cols)
        float sacc[4][4];
        #pragma unroll
        for (int f = 0; f < 4; f++)
            #pragma unroll
            for (int j = 0; j < 4; j++) sacc[f][j] = 0.f;
        #pragma unroll
        for (int kk = 0; kk < 4; kk++) {
            #pragma unroll
            for (int nq = 0; nq < 2; nq++) {
                uint32_t b0, b1, b2, b3;
                uint32_t addr = Kbase + (uint32_t)(((kk * 16 + lm_krow) * 72 +
                                 warp_h * 32 + nq * 16 + lm_ncol) * 2);
                asm volatile("ldmatrix.sync.aligned.m8n8.x4.trans.shared.b16 {%0,%1,%2,%3}, [%4];"
                    : "=r"(b0), "=r"(b1), "=r"(b2), "=r"(b3) : "r"(addr));
                mma16816(sacc[nq * 2],     qf[kk][0], qf[kk][1], qf[kk][2], qf[kk][3], b0, b1);
                mma16816(sacc[nq * 2 + 1], qf[kk][0], qf[kk][1], qf[kk][2], qf[kk][3], b2, b3);
            }
        }

        // ---- softmax in registers; repack C-frag -> PV A-frag
        uint32_t pa[2][4];
        #pragma unroll
        for (int f = 0; f < 4; f++) {
            int sc  = s0 + warp_h * 32 + f * 8 + tig * 2;
            float p0 = (sc     < TOUT) ? __expf(sacc[f][0] * 0.125f) : 0.f;
            float p1 = (sc + 1 < TOUT) ? __expf(sacc[f][1] * 0.125f) : 0.f;
            float p2 = (sc     < TOUT) ? __expf(sacc[f][2] * 0.125f) : 0.f;
            float p3 = (sc + 1 < TOUT) ? __expf(sacc[f][3] * 0.125f) : 0.f;
            l0 += p0 + p1;
            l1 += p2 + p3;
            __half2 hA = __floats2half2_rn(p0, p1);
            __half2 hB = __floats2half2_rn(p2, p3);
            int kk2 = f >> 1, hi = f & 1;
            pa[kk2][hi * 2]     = *(uint32_t*)&hA;   // row gid,   k 2tig (+8*hi)
            pa[kk2][hi * 2 + 1] = *(uint32_t*)&hB;   // row gid+8
        }

        // ---- ctx += P V  (k = warp's 32 s, full n=64)
        #pragma unroll
        for (int kk2 = 0; kk2 < 2; kk2++) {
            #pragma unroll
            for (int nc = 0; nc < 4; nc++) {
                uint32_t v0, v1, v2, v3;
                uint32_t addr = Vbase + (uint32_t)(((warp_h * 32 + kk2 * 16 + lm_krow) * 72 +
                                 nc * 16 + lm_ncol) * 2);
                asm volatile("ldmatrix.sync.aligned.m8n8.x4.trans.shared.b16 {%0,%1,%2,%3}, [%4];"
                    : "=r"(v0), "=r"(v1), "=r"(v2), "=r"(v3) : "r"(addr));
                mma16816(ctx[nc * 2],     pa[kk2][0], pa[kk2][1], pa[kk2][2], pa[kk2][3], v0, v1);
                mma16816(ctx[nc * 2 + 1], pa[kk2][0], pa[kk2][1], pa[kk2][2], pa[kk2][3], v2, v3);
            }
        }
    }
    __syncthreads();               // loop reads done; smem reusable

    // ---- l reduce (quad shuffles) + store
    l0 += __shfl_xor_sync(0xFFFFFFFF, l0, 1);
    l0 += __shfl_xor_sync(0xFFFFFFFF, l0, 2);
    l1 += __shfl_xor_sync(0xFFFFFFFF, l1, 1);
    l1 += __shfl_xor_sync(0xFFFFFFFF, l1, 2);
    if (tig == 0) {
        redl[warp_h * 64 + warp_m * 16 + gid]     = l0;
        redl[warp_h * 64 + warp_m * 16 + gid + 8] = l1;
    }
    // ---- ctx combine across the two s-halves
    if (warp_h == 0) {
        int r = warp_m * 16 + gid, c2 = tig * 2;
        #pragma unroll
        for (int f = 0; f < 8; f++) {
            int c = f * 8 + c2;
            Sf[r * 68 + c]           = ctx[f][0];
            Sf[r * 68 + c + 1]       = ctx[f][1];
            Sf[(r + 8) * 68 + c]     = ctx[f][2];
            Sf[(r + 8) * 68 + c + 1] = ctx[f][3];
        }
    }
    __syncthreads();
    if (warp_h == 1) {
        int r = warp_m * 16 + gid, c2 = tig * 2;
        #pragma unroll
        for (int f = 0; f < 8; f++) {
            int c = f * 8 + c2;
            Sf[r * 68 + c]           += ctx[f][0];
            Sf[r * 68 + c + 1]       += ctx[f][1];
            Sf[(r + 8) * 68 + c]     += ctx[f][2];
            Sf[(r + 8) * 68 + c + 1] += ctx[f][3];
        }
    }
    for (int j = tid; j < 4096; j += 256) wot_s[j] = d_wot[j];
    __syncthreads();

    // ---- wo + residual epilogue
    int q    = tid & 63;
    int part = tid >> 6;
    int cb   = part * 16;
    float invl = 1.f / (redl[q] + redl[64 + q]);
    float ob[16];
    #pragma unroll
    for (int i = 0; i < 16; i++) ob[i] = 0.f;
    for (int c = 0; c < CO; c++) {
        float cv = Sf[q * 68 + c] * invl;
        const float4* wr = (const float4*)&wot_s[c * 64 + cb];
        float4 w0 = wr[0], w1 = wr[1], w2 = wr[2], w3 = wr[3];
        ob[0]  = fmaf(cv, w0.x, ob[0]);  ob[1]  = fmaf(cv, w0.y, ob[1]);
        ob[2]  = fmaf(cv, w0.z, ob[2]);  ob[3]  = fmaf(cv, w0.w, ob[3]);
        ob[4]  = fmaf(cv, w1.x, ob[4]);  ob[5]  = fmaf(cv, w1.y, ob[5]);
        ob[6]  = fmaf(cv, w1.z, ob[6]);  ob[7]  = fmaf(cv, w1.w, ob[7]);
        ob[8]  = fmaf(cv, w2.x, ob[8]);  ob[9]  = fmaf(cv, w2.y, ob[9]);
        ob[10] = fmaf(cv, w2.z, ob[10]); ob[11] = fmaf(cv, w2.w, ob[11]);
        ob[12] = fmaf(cv, w3.x, ob[12]); ob[13] = fmaf(cv, w3.y, ob[13]);
        ob[14] = fmaf(cv, w3.z, ob[14]); ob[15] = fmaf(cv, w3.w, ob[15]);
    }

    int t = t0 + q;
    if (t < TOUT) {
        #pragma unroll
        for (int i = 0; i < 16; i++) {
            int o = cb + i;
            out[((size_t)b * CO + o) * TOUT + t] =
                d_y[((size_t)b * CO + o) * TOUT + t] + ob[i];
        }
    }
}

// ---------------- launch ----------------
extern "C" void kernel_launch(void* const* d_in, const int* in_sizes, int n_in,
                              void* d_out, int out_size) {
    const float* x      = (const float*)d_in[0];
    const float* conv_w = (const float*)d_in[1];
    const float* conv_b = (const float*)d_in[2];
    const float* gamma  = (const float*)d_in[3];
    const float* beta   = (const float*)d_in[4];
    const float* mean   = (const float*)d_in[5];
    const float* var    = (const float*)d_in[6];
    const float* wq     = (const float*)d_in[7];
    const float* wk     = (const float*)d_in[8];
    const float* wv     = (const float*)d_in[9];
    const float* wo     = (const float*)d_in[10];
    float* out = (float*)d_out;

    prep_weights<<<64, 256>>>(conv_w, conv_b, gamma, beta, mean, var);
    prep_bfrag<<<108, 256>>>(conv_w);
    prep_misc<<<16, 256>>>(wq, wk, wv, wo);

    cudaFuncSetAttribute(conv_mma, cudaFuncAttributeMaxDynamicSharedMemorySize, SM_CONV);
    conv_mma<<<dim3(10, NB), 128, SM_CONV>>>(x);

    cudaFuncSetAttribute(qkv_gemm, cudaFuncAttributeMaxDynamicSharedMemorySize, SM_QKV);
    qkv_gemm<<<dim3(10, NB), 256, SM_QKV>>>();

    cudaFuncSetAttribute(attn_mma, cudaFuncAttributeMaxDynamicSharedMemorySize, SM_ATT2);
    attn_mma<<<dim3(10, NB), 256, SM_ATT2>>>(out);
}

// round 17
// speedup vs baseline: 1.1678x; 1.1678x over previous
#include <cuda_runtime.h>
#include <cuda_fp16.h>
#include <mma.h>
#include <math.h>
#include <stdint.h>

using namespace nvcuda;

#define NB   128
#define CIN  128
#define TIN  2500
#define CO   64
#define KW   27
#define TOUT 625
#define KTOT (CIN * KW)      // 3456
#define NKB2 54              // chunks of 64 K

// ---------------- scratch (device globals; no allocation) ----------------
__device__ __half d_wh[KTOT * 64];            // sign rows [K][o]
__device__ unsigned long long d_ktab64[NKB2 * 8];  // per-K byte: (s<<6)|(r<<4)|a
__device__ float  d_scale[CO];
__device__ float  d_shift[CO];
__device__ float  d_y [NB * CO * TOUT];
__device__ __half d_qh[NB * TOUT * CO];       // (B,T,C)
__device__ __half d_kh[NB * CO * TOUT];       // (B,C,T)
__device__ __half d_vh[NB * TOUT * CO];       // (B,T,C)
__device__ __half d_wqkvh[192 * 128];
__device__ float  d_wot[CO * CO];

__device__ __forceinline__ uint32_t smem_u32(const void* p) {
    uint32_t a;
    asm("{ .reg .u64 t; cvta.to.shared.u64 t, %1; cvt.u32.u64 %0, t; }" : "=r"(a) : "l"(p));
    return a;
}
__device__ __forceinline__ void mma16816(float* c, uint32_t a0, uint32_t a1,
                                         uint32_t a2, uint32_t a3,
                                         uint32_t b0, uint32_t b1) {
    asm volatile(
        "mma.sync.aligned.m16n8k16.row.col.f32.f16.f16.f32 "
        "{%0,%1,%2,%3}, {%4,%5,%6,%7}, {%8,%9}, {%0,%1,%2,%3};"
        : "+f"(c[0]), "+f"(c[1]), "+f"(c[2]), "+f"(c[3])
        : "r"(a0), "r"(a1), "r"(a2), "r"(a3), "r"(b0), "r"(b1));
}
__device__ __forceinline__ void cp4(uint32_t daddr, const void* src, int srcsz) {
    asm volatile("cp.async.ca.shared.global [%0], [%1], 4, %2;"
                 :: "r"(daddr), "l"(src), "r"(srcsz));
}
__device__ __forceinline__ void cp16(uint32_t daddr, const void* src) {
    asm volatile("cp.async.cg.shared.global [%0], [%1], 16;"
                 :: "r"(daddr), "l"(src));
}

// ---------------- prep ----------------
__global__ void prep_weights(const float* __restrict__ w,
                             const float* __restrict__ cb,
                             const float* __restrict__ gamma,
                             const float* __restrict__ beta,
                             const float* __restrict__ mean,
                             const float* __restrict__ var) {
    int o = blockIdx.x;
    __shared__ float red[256];
    const float* wrow = w + o * KTOT;
    float s = 0.f;
    for (int j = threadIdx.x; j < KTOT; j += 256) s += fabsf(wrow[j]);
    red[threadIdx.x] = s;
    __syncthreads();
    for (int st = 128; st > 0; st >>= 1) {
        if (threadIdx.x < st) red[threadIdx.x] += red[threadIdx.x + st];
        __syncthreads();
    }
    float alpha = red[0] * (1.f / KTOT);
    float g = gamma[o] * rsqrtf(var[o] + 1e-5f);
    if (threadIdx.x == 0) {
        d_scale[o] = alpha * g;
        d_shift[o] = (cb[o] - mean[o]) * g + beta[o];
    }
    for (int K = threadIdx.x; K < KTOT; K += 256) {
        float wv = wrow[K];
        float sg = (wv > 0.f) ? 1.f : ((wv < 0.f) ? -1.f : 0.f);
        d_wh[K * 64 + o] = __float2half(sg);
    }
}

__global__ void prep_misc(const float* __restrict__ wq, const float* __restrict__ wk,
                          const float* __restrict__ wv, const float* __restrict__ wo) {
    int gtid = blockIdx.x * blockDim.x + threadIdx.x;
    int gstr = gridDim.x * blockDim.x;
    for (int j = gtid; j < CO * CO; j += gstr) {
        int o = j >> 6, c = j & 63;
        d_wot[c * CO + o] = wo[j];
    }
    for (int j = gtid; j < 192 * 128; j += gstr) {
        int m = j >> 7, k = j & 127;
        float v = 0.f;
        if (m < 64)        { if (k < 64)  v = wq[m * 64 + k]; }
        else if (m < 128)  { if (k < 64)  v = wk[(m - 64) * 64 + k]; }
        else               { if (k >= 64) v = wv[(m - 128) * 64 + (k - 64)]; }
        d_wqkvh[j] = __float2half(v);
    }
    for (int K = gtid; K < KTOT; K += gstr) {
        int ib = K >> 6, e = K & 63;
        int ci = K / 27, k = K - 27 * ci;
        int s  = ci - (64 * ib) / 27;        // 0..3
        ((uint8_t*)d_ktab64)[ib * 64 + e] =
            (uint8_t)((s << 6) | ((k & 3) << 4) | (k >> 2));
    }
}

// ---------------- raw-mma fp16 implicit-GEMM conv + BN + ELU ----------------
// grid (10, 128), 128 threads (4 warps). Double-buffered window/B/koff filled
// via cp.async (no LDG->reg->STS round trip); one sync per iteration.
#define W_OFF    0                    // 2 x 1152 floats = 9216
#define KOFF_OFF 9216                 // 2 x 64 ints = 512
#define CB_OFF   9728                 // 2 x 64*72 half = 18432
#define SM_CONV  28160                // Cs alias 64*68*4 = 17408 at 0

__global__ __launch_bounds__(128) void conv_mma(const float* __restrict__ x) {
    extern __shared__ char smem[];
    float*  Wb     = (float*)(smem + W_OFF);      // [buf][slot*288 + r*72 + a]
    int*    koff_s = (int*)(smem + KOFF_OFF);     // [buf][64]
    __half* Bsb    = (__half*)(smem + CB_OFF);    // [buf][k][o], ld 72
    float*  Cs     = (float*)smem;                // epilogue alias 64x68

    int tid = threadIdx.x, wid = tid >> 5, lid = tid & 31;
    int t0 = blockIdx.x * 64;
    int b  = blockIdx.y;
    int w0 = 4 * t0 - 13;

    const float* xb = x + (size_t)b * CIN * TIN;
    uint32_t Wbase = smem_u32(Wb);
    uint32_t Bbase = smem_u32(Bsb);
    int g  = lid >> 3, i5 = lid & 7;
    int lm_krow = i5 + (g & 1) * 8;
    int lm_ncol = (g >> 1) * 8;

    float acc[8][4];
    #pragma unroll
    for (int f = 0; f < 8; f++)
        #pragma unroll
        for (int j = 0; j < 4; j++) acc[f][j] = 0.f;

    int tA = wid * 16 + (lid >> 2);     // A row for this lane

    // issue async fill of buffer `buf` for chunk ibn (cp.async + koff ST)
    auto prefetch = [&](int ibn, int buf) {
        int ci0 = (64 * ibn) / 27;
        #pragma unroll
        for (int i = 0; i < 9; i++) {
            int j2 = tid + i * 128;
            if (j2 < 1152) {
                int slot = j2 / 288, j = j2 - slot * 288;
                int ci = ci0 + slot, gp = w0 + j;
                bool ok = (j < 279) && (ci < CIN) && ((unsigned)gp < (unsigned)TIN);
                uint32_t daddr = Wbase + (uint32_t)((buf * 1152 +
                                 slot * 288 + (j & 3) * 72 + (j >> 2)) * 4);
                const float* src = ok ? (xb + ci * TIN + gp) : xb;
                cp4(daddr, src, ok ? 4 : 0);
            }
        }
        const char* bsrc = (const char*)(d_wh + ibn * 4096);
        #pragma unroll
        for (int e = 0; e < 4; e++) {
            int idx = tid + e * 128;
            int r = idx >> 3, sg = idx & 7;
            cp16(Bbase + (uint32_t)((buf * 4608 + r * 72 + sg * 8) * 2),
                 bsrc + idx * 16);
        }
        if (tid < 64) {
            int pk = ((const uint8_t*)d_ktab64)[ibn * 64 + tid];
            koff_s[buf * 64 + tid] =
                (pk >> 6) * 288 + ((pk >> 4) & 3) * 72 + (pk & 15);
        }
        asm volatile("cp.async.commit_group;" ::: "memory");
    };

    auto compute = [&](int buf) {
        const float* W  = Wb + buf * 1152;
        const int*   ko = koff_s + buf * 64;
        uint32_t Bb = Bbase + (uint32_t)(buf * 9216);
        #pragma unroll
        for (int kk = 0; kk < 4; kk++) {
            int kb0 = kk * 16 + (lid & 3) * 2;
            int o0 = ko[kb0], o1 = ko[kb0 + 1];
            int o2 = ko[kb0 + 8], o3 = ko[kb0 + 9];
            __half2 h;
            uint32_t a0, a1, a2, a3;
            h = __floats2half2_rn(W[o0 + tA],     W[o1 + tA]);     a0 = *(uint32_t*)&h;
            h = __floats2half2_rn(W[o0 + tA + 8], W[o1 + tA + 8]); a1 = *(uint32_t*)&h;
            h = __floats2half2_rn(W[o2 + tA],     W[o3 + tA]);     a2 = *(uint32_t*)&h;
            h = __floats2half2_rn(W[o2 + tA + 8], W[o3 + tA + 8]); a3 = *(uint32_t*)&h;

            #pragma unroll
            for (int np = 0; np < 4; np++) {
                uint32_t b0, b1, b2, b3;
                uint32_t baddr = Bb +
                    (uint32_t)(((kk * 16 + lm_krow) * 72 + np * 16 + lm_ncol) * 2);
                asm volatile(
                    "ldmatrix.sync.aligned.m8n8.x4.trans.shared.b16 "
                    "{%0,%1,%2,%3}, [%4];"
                    : "=r"(b0), "=r"(b1), "=r"(b2), "=r"(b3) : "r"(baddr));
                mma16816(acc[np * 2],     a0, a1, a2, a3, b0, b1);
                mma16816(acc[np * 2 + 1], a0, a1, a2, a3, b2, b3);
            }
        }
    };

    // ---- software pipeline: one sync per iteration ----
    prefetch(0, 0);
    asm volatile("cp.async.wait_group 0;" ::: "memory");
    __syncthreads();

    for (int ib = 0; ib < NKB2; ib++) {
        int buf = ib & 1;
        if (ib + 1 < NKB2) prefetch(ib + 1, buf ^ 1);   // copies fly under compute
        compute(buf);
        if (ib + 1 < NKB2)
            asm volatile("cp.async.wait_group 0;" ::: "memory");
        __syncthreads();                                 // publish buf^1
    }

    // accum -> Cs (aliases W/B; last sync above guards it)
    {
        int r = wid * 16 + (lid >> 2);
        int cb2 = (lid & 3) * 2;
        #pragma unroll
        for (int f = 0; f < 8; f++) {
            int c = f * 8 + cb2;
            Cs[r * 68 + c]           = acc[f][0];
            Cs[r * 68 + c + 1]       = acc[f][1];
            Cs[(r + 8) * 68 + c]     = acc[f][2];
            Cs[(r + 8) * 68 + c + 1] = acc[f][3];
        }
    }
    __syncthreads();

    #pragma unroll
    for (int it = 0; it < 32; it++) {
        int idx = it * 128 + tid;
        int o  = idx >> 6;
        int tl = idx & 63;
        int t  = t0 + tl;
        if (t < TOUT) {
            float v = Cs[tl * 68 + o] * __ldg(d_scale + o) + __ldg(d_shift + o);
            v = (v > 0.f) ? v : expm1f(v);
            d_y[((size_t)b * CO + o) * TOUT + t] = v;
        }
    }
}

// ---------------- qkv as one wmma GEMM: [192x128] x [128x64] ----------------
#define BLD  72
#define QB_OFF 0
#define QA_OFF 18432
#define QC_OFF 18432
#define SM_QKV (18432 + 52224)

__global__ __launch_bounds__(256) void qkv_gemm() {
    extern __shared__ char smem[];
    __half* Bh = (__half*)(smem + QB_OFF);
    __half* Ah = (__half*)(smem + QA_OFF);
    float*  Cs = (float*)(smem + QC_OFF);

    int t0  = blockIdx.x * 64;
    int b   = blockIdx.y;
    int tid = threadIdx.x;
    int wid = tid >> 5;
    int warp_m = wid & 3;
    int warp_n = wid >> 2;

    for (int j = tid; j < 4096; j += 256) {
        int c = j >> 6, tl = j & 63;
        int t = t0 + tl;
        float yv = (t < TOUT) ? d_y[((size_t)b * CO + c) * TOUT + t] : 0.f;
        Bh[c * BLD + tl]        = __float2half(yv > 0.f ? 1.f : 0.f);
        Bh[(64 + c) * BLD + tl] = __float2half(yv);
    }
    {
        const int4* asrc = (const int4*)d_wqkvh;
        #pragma unroll
        for (int e = 0; e < 12; e++) {
            int idx = tid + e * 256;
            int m = idx >> 4, seg = idx & 15;
            *(int4*)&Ah[m * 136 + seg * 8] = __ldg(asrc + idx);
        }
    }
    __syncthreads();

    wmma::fragment<wmma::accumulator, 16, 16, 16, float> acc[3][2];
    #pragma unroll
    for (int i = 0; i < 3; i++)
        #pragma unroll
        for (int j = 0; j < 2; j++) wmma::fill_fragment(acc[i][j], 0.f);

    #pragma unroll
    for (int kk = 0; kk < 8; kk++) {
        wmma::fragment<wmma::matrix_a, 16, 16, 16, __half, wmma::row_major> af[3];
        wmma::fragment<wmma::matrix_b, 16, 16, 16, __half, wmma::row_major> bf[2];
        #pragma unroll
        for (int i = 0; i < 3; i++)
            wmma::load_matrix_sync(af[i], Ah + (warp_m * 48 + i * 16) * 136 + kk * 16, 136);
        #pragma unroll
        for (int j = 0; j < 2; j++)
            wmma::load_matrix_sync(bf[j], Bh + (kk * 16) * BLD + warp_n * 32 + j * 16, BLD);
        #pragma unroll
        for (int i = 0; i < 3; i++)
            #pragma unroll
            for (int j = 0; j < 2; j++)
                wmma::mma_sync(acc[i][j], af[i], bf[j], acc[i][j]);
    }
    __syncthreads();

    #pragma unroll
    for (int i = 0; i < 3; i++)
        #pragma unroll
        for (int j = 0; j < 2; j++)
            wmma::store_matrix_sync(Cs + (warp_m * 48 + i * 16) * 68 + warp_n * 32 + j * 16,
                                    acc[i][j], 68, wmma::mem_row_major);
    __syncthreads();

    for (int j = tid; j < 4096; j += 256) {
        int tl = j >> 6, o = j & 63;
        int t = t0 + tl;
        if (t < TOUT) d_qh[((size_t)b * TOUT + t) * CO + o] = __float2half(Cs[o * 68 + tl]);
    }
    for (int j = tid; j < 4096; j += 256) {
        int o = j >> 6, tl = j & 63;
        int t = t0 + tl;
        if (t < TOUT) d_kh[((size_t)b * CO + o) * TOUT + t] = __float2half(Cs[(64 + o) * 68 + tl]);
    }
    for (int j = tid; j < 4096; j += 256) {
        int tl = j >> 6, o = j & 63;
        int t = t0 + tl;
        if (t < TOUT) d_vh[((size_t)b * TOUT + t) * CO + o] = __float2half(Cs[(128 + o) * 68 + tl]);
    }
}

// ---------------- wmma attention (fixed-shift softmax) + wo + residual ----------------
#define QH_OFF   0
#define KH_OFF   9216
#define VH_OFF   18432
#define PH_OFF   27648
#define SF_OFF   36864
#define RL_OFF   54272
#define SM_ATT   55296

__global__ __launch_bounds__(256) void attn_wmma(float* __restrict__ out) {
    extern __shared__ char smem[];
    __half* Qh = (__half*)(smem + QH_OFF);
    __half* Kh = (__half*)(smem + KH_OFF);
    __half* Vh = (__half*)(smem + VH_OFF);
    __half* Ph = (__half*)(smem + PH_OFF);
    float*  Sf = (float*)(smem + SF_OFF);
    float*  redl = (float*)(smem + RL_OFF);
    float*  wot_s = (float*)(smem + QH_OFF);

    int t0   = blockIdx.x * 64;
    int b    = blockIdx.y;
    int tid  = threadIdx.x;
    int wid  = tid >> 5;
    int q    = tid & 63;
    int part = tid >> 6;
    int cb   = part * 16;
    int warp_m = wid & 3;
    int warp_n = wid >> 2;

    for (int j = tid; j < 4096; j += 256) {
        int tl = j >> 6, c = j & 63;
        int t = t0 + tl;
        Qh[tl * 72 + c] = (t < TOUT) ? d_qh[((size_t)b * TOUT + t) * CO + c]
                                     : __float2half(0.f);
    }

    wmma::fragment<wmma::accumulator, 16, 16, 16, float> ctx[2];
    #pragma unroll
    for (int j = 0; j < 2; j++) wmma::fill_fragment(ctx[j], 0.f);

    float l = 0.f;

    for (int stile = 0; stile < 10; stile++) {
        int s0 = stile * 64;
        __syncthreads();

        for (int j = tid; j < 4096; j += 256) {
            int c = j >> 6, sl = j & 63;
            int s = s0 + sl;
            Kh[c * 72 + sl] = (s < TOUT) ? d_kh[((size_t)b * CO + c) * TOUT + s]
                                         : __float2half(0.f);
        }
        for (int j = tid; j < 4096; j += 256) {
            int sl = j >> 6, c = j & 63;
            int s = s0 + sl;
            Vh[sl * 72 + c] = (s < TOUT) ? d_vh[((size_t)b * TOUT + s) * CO + c]
                                         : __float2half(0.f);
        }
        __syncthreads();

        {
            wmma::fragment<wmma::accumulator, 16, 16, 16, float> sacc[2];
            #pragma unroll
            for (int j = 0; j < 2; j++) wmma::fill_fragment(sacc[j], 0.f);
            #pragma unroll
            for (int kk = 0; kk < 4; kk++) {
                wmma::fragment<wmma::matrix_a, 16, 16, 16, __half, wmma::row_major> af;
                wmma::fragment<wmma::matrix_b, 16, 16, 16, __half, wmma::row_major> bf[2];
                wmma::load_matrix_sync(af, Qh + (warp_m * 16) * 72 + kk * 16, 72);
                #pragma unroll
                for (int j = 0; j < 2; j++)
                    wmma::load_matrix_sync(bf[j], Kh + (kk * 16) * 72 + warp_n * 32 + j * 16, 72);
                #pragma unroll
                for (int j = 0; j < 2; j++)
                    wmma::mma_sync(sacc[j], af, bf[j], sacc[j]);
            }
            #pragma unroll
            for (int j = 0; j < 2; j++)
                wmma::store_matrix_sync(Sf + (warp_m * 16) * 68 + warp_n * 32 + j * 16,
                                        sacc[j], 68, wmma::mem_row_major);
        }
        __syncthreads();

        {
            float lp = 0.f;
            const float4* sr = (const float4*)&Sf[q * 68 + cb];
            float4 s4[4] = { sr[0], sr[1], sr[2], sr[3] };
            float sv[16] = { s4[0].x, s4[0].y, s4[0].z, s4[0].w,
                             s4[1].x, s4[1].y, s4[1].z, s4[1].w,
                             s4[2].x, s4[2].y, s4[2].z, s4[2].w,
                             s4[3].x, s4[3].y, s4[3].z, s4[3].w };
            #pragma unroll
            for (int i = 0; i < 16; i++) {
                int sg = s0 + cb + i;
                float p = (sg < TOUT) ? __expf(sv[i] * 0.125f) : 0.f;
                Ph[q * 72 + cb + i] = __float2half(p);
                lp += p;
            }
            redl[part * 64 + q] = lp;
        }
        __syncthreads();

        l += redl[q] + redl[64 + q] + redl[128 + q] + redl[192 + q];

        #pragma unroll
        for (int kk = 0; kk < 4; kk++) {
            wmma::fragment<wmma::matrix_a, 16, 16, 16, __half, wmma::row_major> af;
            wmma::fragment<wmma::matrix_b, 16, 16, 16, __half, wmma::row_major> bf[2];
            wmma::load_matrix_sync(af, Ph + (warp_m * 16) * 72 + kk * 16, 72);
            #pragma unroll
            for (int j = 0; j < 2; j++)
                wmma::load_matrix_sync(bf[j], Vh + (kk * 16) * 72 + warp_n * 32 + j * 16, 72);
            #pragma unroll
            for (int j = 0; j < 2; j++)
                wmma::mma_sync(ctx[j], af, bf[j], ctx[j]);
        }
    }

    __syncthreads();
    #pragma unroll
    for (int j = 0; j < 2; j++)
        wmma::store_matrix_sync(Sf + (warp_m * 16) * 68 + warp_n * 32 + j * 16,
                                ctx[j], 68, wmma::mem_row_major);
    for (int j = tid; j < 4096; j += 256) wot_s[j] = d_wot[j];
    __syncthreads();

    float invl = 1.f / l;
    float ob[16];
    #pragma unroll
    for (int i = 0; i < 16; i++) ob[i] = 0.f;
    for (int c = 0; c < CO; c++) {
        float cv = Sf[q * 68 + c] * invl;
        const float4* wr = (const float4*)&wot_s[c * 64 + cb];
        float4 w0 = wr[0], w1 = wr[1], w2 = wr[2], w3 = wr[3];
        ob[0]  = fmaf(cv, w0.x, ob[0]);  ob[1]  = fmaf(cv, w0.y, ob[1]);
        ob[2]  = fmaf(cv, w0.z, ob[2]);  ob[3]  = fmaf(cv, w0.w, ob[3]);
        ob[4]  = fmaf(cv, w1.x, ob[4]);  ob[5]  = fmaf(cv, w1.y, ob[5]);
        ob[6]  = fmaf(cv, w1.z, ob[6]);  ob[7]  = fmaf(cv, w1.w, ob[7]);
        ob[8]  = fmaf(cv, w2.x, ob[8]);  ob[9]  = fmaf(cv, w2.y, ob[9]);
        ob[10] = fmaf(cv, w2.z, ob[10]); ob[11] = fmaf(cv, w2.w, ob[11]);
        ob[12] = fmaf(cv, w3.x, ob[12]); ob[13] = fmaf(cv, w3.y, ob[13]);
        ob[14] = fmaf(cv, w3.z, ob[14]); ob[15] = fmaf(cv, w3.w, ob[15]);
    }

    int t = t0 + q;
    if (t < TOUT) {
        #pragma unroll
        for (int i = 0; i < 16; i++) {
            int o = cb + i;
            out[((size_t)b * CO + o) * TOUT + t] =
                d_y[((size_t)b * CO + o) * TOUT + t] + ob[i];
        }
    }
}

// ---------------- launch ----------------
extern "C" void kernel_launch(void* const* d_in, const int* in_sizes, int n_in,
                              void* d_out, int out_size) {
    const float* x      = (const float*)d_in[0];
    const float* conv_w = (const float*)d_in[1];
    const float* conv_b = (const float*)d_in[2];
    const float* gamma  = (const float*)d_in[3];
    const float* beta   = (const float*)d_in[4];
    const float* mean   = (const float*)d_in[5];
    const float* var    = (const float*)d_in[6];
    const float* wq     = (const float*)d_in[7];
    const float* wk     = (const float*)d_in[8];
    const float* wv     = (const float*)d_in[9];
    const float* wo     = (const float*)d_in[10];
    float* out = (float*)d_out;

    prep_weights<<<64, 256>>>(conv_w, conv_b, gamma, beta, mean, var);
    prep_misc<<<16, 256>>>(wq, wk, wv, wo);

    cudaFuncSetAttribute(conv_mma, cudaFuncAttributeMaxDynamicSharedMemorySize, SM_CONV);
    conv_mma<<<dim3(10, NB), 128, SM_CONV>>>(x);

    cudaFuncSetAttribute(qkv_gemm, cudaFuncAttributeMaxDynamicSharedMemorySize, SM_QKV);
    qkv_gemm<<<dim3(10, NB), 256, SM_QKV>>>();

    cudaFuncSetAttribute(attn_wmma, cudaFuncAttributeMaxDynamicSharedMemorySize, SM_ATT);
    attn_wmma<<<dim3(10, NB), 256, SM_ATT>>>(out);
}